// round 2
// baseline (speedup 1.0000x reference)
#include <cuda_runtime.h>
#include <cuda_bf16.h>

// Problem constants
#define Bn 4
#define Hn 480
#define Wn 640
#define HWn (Hn * Wn)          // 307200
#define PWn (Wn + 2)           // 642
#define PHn (Hn + 2)           // 482
#define PHWn (PHn * PWn)       // 309444
#define PROP_TIME 18

// Static device scratch (allocation-free rule): ping-pong padded feature
// buffers g = f * conf_eff, and normalized affinities (8 ch).
__device__ float g_bufA[Bn * PHWn];
__device__ float g_bufB[Bn * PHWn];
__device__ float g_aff8[Bn * 8 * HWn];

// ---------------------------------------------------------------------------
// Precompute kernel: grid over padded size.
//  - zero the borders of BOTH ping-pong buffers (idempotent; replayed in graph)
//  - interior: normalize affinities, build f0 = blend(feat_init, feat_fix),
//    conf_eff = blend(confidence, 1), write g0 = f0 * conf_eff into bufA.
// ---------------------------------------------------------------------------
__global__ __launch_bounds__(256)
void prep_kernel(const float* __restrict__ feat_init,
                 const float* __restrict__ guid,
                 const float* __restrict__ conf,
                 const float* __restrict__ fix,
                 const float* __restrict__ scale_ptr)
{
    int idx = blockIdx.x * blockDim.x + threadIdx.x;
    if (idx >= Bn * PHWn) return;
    int b = idx / PHWn;
    int r = idx - b * PHWn;
    int yy = r / PWn;
    int xx = r - yy * PWn;

    if (yy == 0 || yy == PHn - 1 || xx == 0 || xx == PWn - 1) {
        g_bufA[idx] = 0.0f;
        g_bufB[idx] = 0.0f;
        return;
    }
    int y = yy - 1, x = xx - 1;
    int pix = y * Wn + x;

    // Affinity normalization (guidance channels 16..23)
    float scale = scale_ptr[0] + 1e-8f;
    float inv_scale = 1.0f / scale;
    const float* gbase = guid + ((size_t)b * 24) * HWn + pix;
    float a[8];
    float s = 1e-4f;
#pragma unroll
    for (int k = 0; k < 8; k++) {
        float v = tanhf(gbase[(16 + k) * HWn]) * inv_scale;
        a[k] = v;
        s += fabsf(v);
    }
    s = fmaxf(s, 1.0f);
    float invs = 1.0f / s;
    float* abase = g_aff8 + ((size_t)b * 8) * HWn + pix;
#pragma unroll
    for (int k = 0; k < 8; k++) {
        abase[k * HWn] = a[k] * invs;
    }

    int gidx = b * HWn + pix;
    float fv = fix[gidx];
    bool m = fv > 0.0f;
    float f0 = m ? fv : feat_init[gidx];
    float ce = m ? 1.0f : conf[gidx];
    g_bufA[idx] = f0 * ce;
}

// ---------------------------------------------------------------------------
// One propagation step. Reads gIn (padded, zero border), writes gOut padded
// interior; on the final step writes f' to d_out instead.
// srcIsA selects ping-pong direction; write_out selects final step.
// ---------------------------------------------------------------------------
__global__ __launch_bounds__(256)
void iter_kernel(const float* __restrict__ guid,
                 const float* __restrict__ fix,
                 const float* __restrict__ conf,
                 float* __restrict__ outF,
                 int srcIsA, int write_out)
{
    int idx = blockIdx.x * blockDim.x + threadIdx.x;
    if (idx >= Bn * HWn) return;
    int b = idx / HWn;
    int r = idx - b * HWn;
    int y = r / Wn;
    int x = r - y * Wn;

    const float* __restrict__ gIn = (srcIsA ? g_bufA : g_bufB) + (size_t)b * PHWn;
    const float* __restrict__ gch = guid + ((size_t)b * 24) * HWn + r;
    const float* __restrict__ ach = g_aff8 + ((size_t)b * 8) * HWn + r;

    float acc = 0.0f;
    float asum = 0.0f;

    // 8 non-center taps; tap t maps to 3x3 position kt (skipping center 4)
#pragma unroll
    for (int t = 0; t < 8; t++) {
        const int kt = (t < 4) ? t : t + 1;
        const float ky = (float)(kt / 3 - 1);
        const float kx = (float)(kt % 3 - 1);

        float dy = gch[(2 * t) * HWn];
        float dx = gch[(2 * t + 1) * HWn];
        float av = ach[t * HWn];

        float py = (float)y + ky + dy;
        float px = (float)x + kx + dx;
        float y0f = floorf(py);
        float x0f = floorf(px);
        float wy = py - y0f;
        float wx = px - x0f;
        int iy = (int)y0f;
        int ix = (int)x0f;

        float v = 0.0f;
        if (iy >= -1 && iy <= Hn - 1 && ix >= -1 && ix <= Wn - 1) {
            const float* p = gIn + (iy + 1) * PWn + (ix + 1);
            float v00 = p[0];
            float v01 = p[1];
            float v10 = p[PWn];
            float v11 = p[PWn + 1];
            float top = fmaf(wx, v01 - v00, v00);
            float bot = fmaf(wx, v11 - v10, v10);
            v = fmaf(wy, bot - top, top);
        }
        acc = fmaf(av, v, acc);
        asum += av;
    }

    // Center tap: exact sample, affinity = 1 - sum(aff8)
    float c = gIn[(y + 1) * PWn + (x + 1)];
    acc = fmaf(1.0f - asum, c, acc);

    float fv = fix[idx];
    bool m = fv > 0.0f;
    float fn = m ? fv : acc;

    if (write_out) {
        outF[idx] = fn;
    } else {
        float ce = m ? 1.0f : conf[idx];
        float* gOut = (srcIsA ? g_bufB : g_bufA);
        gOut[(size_t)b * PHWn + (y + 1) * PWn + (x + 1)] = fn * ce;
    }
}

extern "C" void kernel_launch(void* const* d_in, const int* in_sizes, int n_in,
                              void* d_out, int out_size)
{
    const float* feat_init = (const float*)d_in[0];
    const float* guidance  = (const float*)d_in[1];
    const float* confidence= (const float*)d_in[2];
    const float* feat_fix  = (const float*)d_in[3];
    const float* aff_scale = (const float*)d_in[4];
    float* out = (float*)d_out;

    const int threads = 256;
    const int prep_blocks = (Bn * PHWn + threads - 1) / threads;
    const int iter_blocks = (Bn * HWn + threads - 1) / threads;

    prep_kernel<<<prep_blocks, threads>>>(feat_init, guidance, confidence,
                                          feat_fix, aff_scale);

    int srcIsA = 1;
    for (int t = 0; t < PROP_TIME; t++) {
        int last = (t == PROP_TIME - 1) ? 1 : 0;
        iter_kernel<<<iter_blocks, threads>>>(guidance, feat_fix, confidence,
                                              out, srcIsA, last);
        srcIsA ^= 1;
    }
}

// round 3
// speedup vs baseline: 1.2226x; 1.2226x over previous
#include <cuda_runtime.h>
#include <cuda_bf16.h>

// Problem constants
#define Bn 4
#define Hn 480
#define Wn 640
#define HWn (Hn * Wn)          // 307200
#define PWn (Wn + 2)           // 642
#define PHn (Hn + 2)           // 482
#define PHWn (PHn * PWn)       // 309444
#define PROP_TIME 18

// Out-of-bounds sentinel: row 481 (zero border); its +PWn neighbors land in the
// next batch's row 0 (also zero border) or, for the last batch, in the zero tail.
#define OOB_OFF ((PHn - 1) * PWn)   // 308802
#define TAIL 64

// Static device scratch (allocation-free rule).
// Ping-pong padded feature buffers g = f * conf_eff (zero borders + zero tail).
__device__ float g_bufA[Bn * PHWn + TAIL];
__device__ float g_bufB[Bn * PHWn + TAIL];
// Packed per-tap data, layout [b][tap][pix], 8 bytes per entry:
//   lo: off(19 bits) | wxq(13 bits)<<19
//   hi: wyq(13 bits) | affq(19-bit signed)<<13
__device__ ulonglong2 g_taps[Bn * 8 * HWn / 2];
// Fused fix/conf stream: q<0 -> fixed pixel with value -q; q>=0 -> conf=q.
__device__ float g_q[Bn * HWn];

// ---------------------------------------------------------------------------
// Precompute kernel (runs once per graph replay; all writes idempotent).
// ---------------------------------------------------------------------------
__global__ __launch_bounds__(256)
void prep_kernel(const float* __restrict__ feat_init,
                 const float* __restrict__ guid,
                 const float* __restrict__ conf,
                 const float* __restrict__ fix,
                 const float* __restrict__ scale_ptr)
{
    int idx = blockIdx.x * blockDim.x + threadIdx.x;
    if (idx >= Bn * PHWn + TAIL) return;

    if (idx >= Bn * PHWn) {            // zero tail
        g_bufA[idx] = 0.0f;
        g_bufB[idx] = 0.0f;
        return;
    }
    int b = idx / PHWn;
    int r = idx - b * PHWn;
    int yy = r / PWn;
    int xx = r - yy * PWn;

    if (yy == 0 || yy == PHn - 1 || xx == 0 || xx == PWn - 1) {
        g_bufA[idx] = 0.0f;
        g_bufB[idx] = 0.0f;
        return;
    }
    int y = yy - 1, x = xx - 1;
    int pix = y * Wn + x;

    // Affinity normalization (guidance channels 16..23)
    float scale = scale_ptr[0] + 1e-8f;
    float inv_scale = 1.0f / scale;
    const float* gbase = guid + ((size_t)b * 24) * HWn + pix;
    float a[8];
    float s = 1e-4f;
#pragma unroll
    for (int k = 0; k < 8; k++) {
        float v = tanhf(gbase[(16 + k) * HWn]) * inv_scale;
        a[k] = v;
        s += fabsf(v);
    }
    s = fmaxf(s, 1.0f);
    float invs = 1.0f / s;

    // Build packed taps
#pragma unroll
    for (int t = 0; t < 8; t++) {
        const int kt = (t < 4) ? t : t + 1;
        const float ky = (float)(kt / 3 - 1);
        const float kx = (float)(kt % 3 - 1);

        float dy = gbase[(2 * t) * HWn];
        float dx = gbase[(2 * t + 1) * HWn];

        float py = (float)y + ky + dy;
        float px = (float)x + kx + dx;
        float y0f = floorf(py);
        float x0f = floorf(px);
        int iy = (int)y0f;
        int ix = (int)x0f;
        float wy = py - y0f;
        float wx = px - x0f;

        bool valid = (iy >= -1) & (iy <= Hn - 1) & (ix >= -1) & (ix <= Wn - 1);
        unsigned int off = valid ? (unsigned int)((iy + 1) * PWn + (ix + 1))
                                 : (unsigned int)OOB_OFF;
        int wxq = min((int)(wx * 8192.0f + 0.5f), 8191);
        int wyq = min((int)(wy * 8192.0f + 0.5f), 8191);
        int affq = (int)rintf(a[t] * invs * 131072.0f);

        unsigned int lo = off | ((unsigned int)wxq << 19);
        unsigned int hi = (unsigned int)wyq | ((unsigned int)affq << 13);

        // store as half of a ulonglong2 (layout [b][t][pix])
        unsigned long long word = ((unsigned long long)hi << 32) | lo;
        unsigned long long* tp =
            reinterpret_cast<unsigned long long*>(g_taps) +
            ((size_t)(b * 8 + t) * HWn + pix);
        *tp = word;
    }

    int gidx = b * HWn + pix;
    float fv = fix[gidx];
    bool m = fv > 0.0f;
    float cf = conf[gidx];
    float f0 = m ? fv : feat_init[gidx];
    float ce = m ? 1.0f : cf;
    g_bufA[idx] = f0 * ce;
    g_q[gidx] = m ? -fv : cf;
}

// ---------------------------------------------------------------------------
// One propagation step: 2 pixels per thread, 16B tap loads.
// ---------------------------------------------------------------------------
__global__ __launch_bounds__(256)
void iter_kernel(float* __restrict__ outF, int srcIsA, int write_out)
{
    int i = blockIdx.x * blockDim.x + threadIdx.x;
    if (i >= Bn * HWn / 2) return;
    int p = i * 2;
    int b = p / HWn;
    int r = p - b * HWn;
    int y = r / Wn;
    int x = r - y * Wn;

    const float* __restrict__ gIn = (srcIsA ? g_bufA : g_bufB) + (size_t)b * PHWn;
    const ulonglong2* __restrict__ taps = g_taps + (size_t)b * 8 * (HWn / 2) + (r >> 1);

    float acc0 = 0.0f, acc1 = 0.0f;
    float asum0 = 0.0f, asum1 = 0.0f;

#pragma unroll
    for (int t = 0; t < 8; t++) {
        ulonglong2 tv = taps[t * (HWn / 2)];

        // pixel 0
        {
            unsigned int lo = (unsigned int)tv.x;
            unsigned int hi = (unsigned int)(tv.x >> 32);
            unsigned int off = lo & 0x7FFFFu;
            float wx = (float)(lo >> 19) * (1.0f / 8192.0f);
            float wy = (float)(hi & 0x1FFFu) * (1.0f / 8192.0f);
            float av = (float)(((int)hi) >> 13) * (1.0f / 131072.0f);
            const float* pp = gIn + off;
            float v00 = pp[0];
            float v01 = pp[1];
            float v10 = pp[PWn];
            float v11 = pp[PWn + 1];
            float top = fmaf(wx, v01 - v00, v00);
            float bot = fmaf(wx, v11 - v10, v10);
            float v = fmaf(wy, bot - top, top);
            acc0 = fmaf(av, v, acc0);
            asum0 += av;
        }
        // pixel 1
        {
            unsigned int lo = (unsigned int)tv.y;
            unsigned int hi = (unsigned int)(tv.y >> 32);
            unsigned int off = lo & 0x7FFFFu;
            float wx = (float)(lo >> 19) * (1.0f / 8192.0f);
            float wy = (float)(hi & 0x1FFFu) * (1.0f / 8192.0f);
            float av = (float)(((int)hi) >> 13) * (1.0f / 131072.0f);
            const float* pp = gIn + off;
            float v00 = pp[0];
            float v01 = pp[1];
            float v10 = pp[PWn];
            float v11 = pp[PWn + 1];
            float top = fmaf(wx, v01 - v00, v00);
            float bot = fmaf(wx, v11 - v10, v10);
            float v = fmaf(wy, bot - top, top);
            acc1 = fmaf(av, v, acc1);
            asum1 += av;
        }
    }

    // Center taps (exact samples; affinity = 1 - sum of the 8 stored affs)
    int cbase = (y + 1) * PWn + (x + 1);
    float c0 = gIn[cbase];
    float c1 = gIn[cbase + 1];
    acc0 = fmaf(1.0f - asum0, c0, acc0);
    acc1 = fmaf(1.0f - asum1, c1, acc1);

    float2 qv = *reinterpret_cast<const float2*>(g_q + p);
    bool m0 = qv.x < 0.0f;
    bool m1 = qv.y < 0.0f;
    float fn0 = m0 ? -qv.x : acc0;
    float fn1 = m1 ? -qv.y : acc1;

    if (write_out) {
        *reinterpret_cast<float2*>(outF + p) = make_float2(fn0, fn1);
    } else {
        float g0 = m0 ? fn0 : fn0 * qv.x;   // conf_eff = 1 for fixed, conf otherwise
        float g1 = m1 ? fn1 : fn1 * qv.y;
        float* gOut = (srcIsA ? g_bufB : g_bufA) + (size_t)b * PHWn;
        gOut[cbase] = g0;
        gOut[cbase + 1] = g1;
    }
}

extern "C" void kernel_launch(void* const* d_in, const int* in_sizes, int n_in,
                              void* d_out, int out_size)
{
    const float* feat_init  = (const float*)d_in[0];
    const float* guidance   = (const float*)d_in[1];
    const float* confidence = (const float*)d_in[2];
    const float* feat_fix   = (const float*)d_in[3];
    const float* aff_scale  = (const float*)d_in[4];
    float* out = (float*)d_out;

    const int threads = 256;
    const int prep_blocks = (Bn * PHWn + TAIL + threads - 1) / threads;
    const int iter_blocks = (Bn * HWn / 2 + threads - 1) / threads;

    prep_kernel<<<prep_blocks, threads>>>(feat_init, guidance, confidence,
                                          feat_fix, aff_scale);

    int srcIsA = 1;
    for (int t = 0; t < PROP_TIME; t++) {
        int last = (t == PROP_TIME - 1) ? 1 : 0;
        iter_kernel<<<iter_blocks, threads>>>(out, srcIsA, last);
        srcIsA ^= 1;
    }
}